// round 14
// baseline (speedup 1.0000x reference)
#include <cuda_runtime.h>
#include <cstdint>

// CostVolume: B=8, C=128, H=128, W=256, d=4 -> out (8, 81, 128, 256) fp32
#define BB   8
#define CC_  128
#define HH   128
#define WW   256
#define SS   9

#define HB   8                 // h rows per CTA tile
#define WB   32                // w cols per CTA tile
#define CCH  16                // channel chunk
#define NCH  (CC_ / CCH)       // 8 chunks
#define F2R  16                // HB + 8 halo rows
#define F2P  40                // f2 row pitch (floats): 10 chunks of 16B
#define F1P  32                // f1 row pitch: 8 chunks
#define NT   288               // 9 di * 8 hh * 4 wo

#define F1_SLICE (HB * F1P)                 // 256 floats per channel
#define F1_ELEMS (CCH * F1_SLICE)           // 4096
#define F2_SLICE (F2R * F2P)                // 640 floats per channel
#define F2_ELEMS (CCH * F2_SLICE)           // 10240
#define STAGE       (F1_ELEMS + F2_ELEMS)   // 14336 floats
#define STAGE_BYTES (STAGE * 4)             // 57344 B
#define SMEM_BYTES  (2 * STAGE_BYTES)       // 114688 B -> 2 CTAs/SM (224KB)

#define CHUNK_ELEMS (CCH * HH * WW)         // 524288 per c-chunk

using u64 = unsigned long long;

__device__ __forceinline__ u64 pack2(float lo, float hi) {
    u64 r;
    asm("mov.b64 %0, {%1, %2};" : "=l"(r) : "f"(lo), "f"(hi));
    return r;
}
__device__ __forceinline__ void unpack2(u64 v, float& lo, float& hi) {
    asm("mov.b64 {%0, %1}, %2;" : "=f"(lo), "=f"(hi) : "l"(v));
}
__device__ __forceinline__ void fma2(u64& acc, u64 a, u64 b) {
    asm("fma.rn.f32x2 %0, %1, %2, %0;" : "+l"(acc) : "l"(a), "l"(b));
}
__device__ __forceinline__ void cp16(uint32_t dst, const void* src, bool ok) {
    int sz = ok ? 16 : 0;
    asm volatile("cp.async.cg.shared.global [%0], [%1], 16, %2;\n"
                 :: "r"(dst), "l"(src), "r"(sz) : "memory");
}

__global__ __launch_bounds__(NT, 2)
void CostVolume_56745107914783_kernel(const float* __restrict__ f1,
                                      const float* __restrict__ f2,
                                      float* __restrict__ out)
{
    extern __shared__ float smem[];

    const int tid = threadIdx.x;
    const int wo  = tid & 3;          // 0..3  w octet (8 outputs each)
    const int hh  = (tid >> 2) & 7;   // 0..7  h within tile
    const int di  = tid >> 5;         // 0..8  h-shift index

    const int w0 = blockIdx.x * WB;
    const int h0 = blockIdx.y * HB;
    const int b  = blockIdx.z;

    const float* f1b = f1 + (size_t)b * CC_ * HH * WW;
    const float* f2b = f2 + (size_t)b * CC_ * HH * WW;

    const uint32_t smem_u32 = (uint32_t)__cvta_generic_to_shared(smem);

    // ---------- affine cp.async role assignment (per-thread constants) ----------
    // threads [0,160): one f2 granule (r, cg) walked over c = 0..15
    // threads [160,224): one f1 granule (h, cg) walked over c = 0..15
    // chunk positions are swizzled: pos = cg ^ (row & 1)   (bank-conflict-free loads)
    uint32_t g_src = 0, s_dst = 0;
    bool g_ok = false;
    const bool is_f2 = (tid < 160);
    const bool is_f1 = (tid >= 160) && (tid < 224);
    if (is_f2) {
        int r  = tid / 10;
        int cg = tid - r * 10;
        int gh = h0 + r - 4;
        int gw = w0 + cg * 4 - 4;
        g_ok  = (gh >= 0) && (gh < HH) && (gw >= 0) && (gw + 4 <= WW);
        g_src = g_ok ? (uint32_t)(gh * WW + gw) : 0u;
        s_dst = (uint32_t)((F1_ELEMS + r * F2P + ((cg ^ (r & 1)) << 2)) * 4);
    } else if (is_f1) {
        int u  = tid - 160;
        int h  = u >> 3;
        int cg = u & 7;
        g_ok  = true;
        g_src = (uint32_t)((h0 + h) * WW + w0 + cg * 4);
        s_dst = (uint32_t)((h * F1P + ((cg ^ (h & 1)) << 2)) * 4);
    }

    auto issue = [&](int ck, int buf) {
        const uint32_t stb = smem_u32 + buf * STAGE_BYTES;
        if (is_f2) {
            const float* src = f2b + (size_t)ck * CHUNK_ELEMS + g_src;
            uint32_t dst = stb + s_dst;
            #pragma unroll
            for (int c = 0; c < CCH; c++) {
                cp16(dst, src, g_ok);
                src += HH * WW;
                dst += F2_SLICE * 4;
            }
        } else if (is_f1) {
            const float* src = f1b + (size_t)ck * CHUNK_ELEMS + g_src;
            uint32_t dst = stb + s_dst;
            #pragma unroll
            for (int c = 0; c < CCH; c++) {
                cp16(dst, src, true);
                src += HH * WW;
                dst += F1_SLICE * 4;
            }
        }
        asm volatile("cp.async.commit_group;" ::: "memory");
    };

    // ------------- accumulators: 9 dj x 4 packed w-pairs (8 outputs) -------------
    u64 acc[SS][4];
    #pragma unroll
    for (int j = 0; j < SS; j++) {
        acc[j][0] = 0ULL; acc[j][1] = 0ULL; acc[j][2] = 0ULL; acc[j][3] = 0ULL;
    }

    // ---------- compute-side smem read offsets (swizzled chunk positions) ----------
    const int r2 = hh + di;                        // f2 row index
    const int rp = r2 & 1;
    const int hp = hh & 1;
    int f1o0 = hh * F1P + (((2 * wo + 0) ^ hp) << 2);
    int f1o1 = hh * F1P + (((2 * wo + 1) ^ hp) << 2);
    int f2o0 = F1_ELEMS + r2 * F2P + (((2 * wo + 0) ^ rp) << 2);
    int f2o1 = F1_ELEMS + r2 * F2P + (((2 * wo + 1) ^ rp) << 2);
    int f2o2 = F1_ELEMS + r2 * F2P + (((2 * wo + 2) ^ rp) << 2);
    int f2o3 = F1_ELEMS + r2 * F2P + (((2 * wo + 3) ^ rp) << 2);

    issue(0, 0);

    for (int ck = 0; ck < NCH; ck++) {
        if (ck + 1 < NCH) {
            issue(ck + 1, (ck + 1) & 1);
            asm volatile("cp.async.wait_group 1;" ::: "memory");
        } else {
            asm volatile("cp.async.wait_group 0;" ::: "memory");
        }
        __syncthreads();

        const float* st = smem + (ck & 1) * STAGE;

        #pragma unroll
        for (int c = 0; c < CCH; c++) {
            const float* s1 = st + c * F1_SLICE;
            const float* s2 = st + c * F2_SLICE;

            // f1: 8 floats -> 4 even pairs
            ulonglong2 pa01 = *reinterpret_cast<const ulonglong2*>(s1 + f1o0);
            ulonglong2 pa23 = *reinterpret_cast<const ulonglong2*>(s1 + f1o1);

            // f2 window: 16 floats as 4 chunks (each float4 + u64-pair view)
            float4 v0 = *reinterpret_cast<const float4*>(s2 + f2o0);
            float4 v1 = *reinterpret_cast<const float4*>(s2 + f2o1);
            float4 v2 = *reinterpret_cast<const float4*>(s2 + f2o2);
            float4 v3 = *reinterpret_cast<const float4*>(s2 + f2o3);
            ulonglong2 e0 = *reinterpret_cast<const ulonglong2*>(s2 + f2o0);
            ulonglong2 e1 = *reinterpret_cast<const ulonglong2*>(s2 + f2o1);
            ulonglong2 e2 = *reinterpret_cast<const ulonglong2*>(s2 + f2o2);
            ulonglong2 e3 = *reinterpret_cast<const ulonglong2*>(s2 + f2o3);

            u64 pv[15];
            pv[0]  = e0.x; pv[2]  = e0.y;
            pv[4]  = e1.x; pv[6]  = e1.y;
            pv[8]  = e2.x; pv[10] = e2.y;
            pv[12] = e3.x; pv[14] = e3.y;
            pv[1]  = pack2(v0.y, v0.z);
            pv[3]  = pack2(v0.w, v1.x);
            pv[5]  = pack2(v1.y, v1.z);
            pv[7]  = pack2(v1.w, v2.x);
            pv[9]  = pack2(v2.y, v2.z);
            pv[11] = pack2(v2.w, v3.x);
            pv[13] = pack2(v3.y, v3.z);

            #pragma unroll
            for (int dj = 0; dj < SS; dj++) {
                fma2(acc[dj][0], pa01.x, pv[dj]);       // outputs w+0,1
                fma2(acc[dj][1], pa01.y, pv[dj + 2]);   // outputs w+2,3
                fma2(acc[dj][2], pa23.x, pv[dj + 4]);   // outputs w+4,5
                fma2(acc[dj][3], pa23.y, pv[dj + 6]);   // outputs w+6,7
            }
        }
        __syncthreads();
    }

    // ------------------------- epilogue: scale + store -------------------------
    const float scale = 1.0f / (float)CC_;
    #pragma unroll
    for (int dj = 0; dj < SS; dj++) {
        int s = di * SS + dj;
        float x0, x1, x2, x3, x4, x5, x6, x7;
        unpack2(acc[dj][0], x0, x1);
        unpack2(acc[dj][1], x2, x3);
        unpack2(acc[dj][2], x4, x5);
        unpack2(acc[dj][3], x6, x7);
        float* dst = out + (((size_t)b * (SS * SS) + s) * HH + (h0 + hh)) * WW
                   + w0 + wo * 8;
        float4 o0, o1;
        o0.x = x0 * scale; o0.y = x1 * scale; o0.z = x2 * scale; o0.w = x3 * scale;
        o1.x = x4 * scale; o1.y = x5 * scale; o1.z = x6 * scale; o1.w = x7 * scale;
        *reinterpret_cast<float4*>(dst)     = o0;
        *reinterpret_cast<float4*>(dst + 4) = o1;
    }
}

extern "C" void kernel_launch(void* const* d_in, const int* in_sizes, int n_in,
                              void* d_out, int out_size) {
    const float* f1 = (const float*)d_in[0];
    const float* f2 = (const float*)d_in[1];
    float* out = (float*)d_out;

    cudaFuncSetAttribute(CostVolume_56745107914783_kernel,
                         cudaFuncAttributeMaxDynamicSharedMemorySize, SMEM_BYTES);

    dim3 grid(WW / WB, HH / HB, BB);   // 8 x 16 x 8 = 1024 CTAs
    CostVolume_56745107914783_kernel<<<grid, NT, SMEM_BYTES>>>(f1, f2, out);
}

// round 15
// speedup vs baseline: 1.0343x; 1.0343x over previous
#include <cuda_runtime.h>
#include <cstdint>

// CostVolume: B=8, C=128, H=128, W=256, d=4 -> out (8, 81, 128, 256) fp32
#define BB   8
#define CC_  128
#define HH   128
#define WW   256
#define SS   9

#define HB   8                 // h rows per CTA tile
#define WB   32                // w cols per CTA tile
#define CCH  16                // channel chunk
#define NCH  (CC_ / CCH)       // 8 chunks
#define F2R  16                // HB + 8 halo rows
#define F2P  40                // f2 row pitch (floats): 10 chunks of 16B
#define F1P  32                // f1 row pitch: 8 chunks
#define NT   288               // 9 di * 8 hh * 4 wo

#define F1_SLICE (HB * F1P)                 // 256 floats per channel
#define F1_ELEMS (CCH * F1_SLICE)           // 4096
#define F2_SLICE (F2R * F2P)                // 640 floats per channel
#define F2_ELEMS (CCH * F2_SLICE)           // 10240
#define STAGE       (F1_ELEMS + F2_ELEMS)   // 14336 floats
#define STAGE_BYTES (STAGE * 4)             // 57344 B
#define SMEM_BYTES  (2 * STAGE_BYTES)       // 114688 B -> 2 CTAs/SM (224KB)

#define CHUNK_ELEMS (CCH * HH * WW)         // 524288 per c-chunk

using u64 = unsigned long long;

__device__ __forceinline__ u64 pack2(float lo, float hi) {
    u64 r;
    asm("mov.b64 %0, {%1, %2};" : "=l"(r) : "f"(lo), "f"(hi));
    return r;
}
__device__ __forceinline__ void unpack2(u64 v, float& lo, float& hi) {
    asm("mov.b64 {%0, %1}, %2;" : "=f"(lo), "=f"(hi) : "l"(v));
}
__device__ __forceinline__ void fma2(u64& acc, u64 a, u64 b) {
    asm("fma.rn.f32x2 %0, %1, %2, %0;" : "+l"(acc) : "l"(a), "l"(b));
}
__device__ __forceinline__ void cp16(uint32_t dst, const void* src, bool ok) {
    int sz = ok ? 16 : 0;
    asm volatile("cp.async.cg.shared.global [%0], [%1], 16, %2;\n"
                 :: "r"(dst), "l"(src), "r"(sz) : "memory");
}

__global__ __launch_bounds__(NT, 2)
void CostVolume_56745107914783_kernel(const float* __restrict__ f1,
                                      const float* __restrict__ f2,
                                      float* __restrict__ out)
{
    extern __shared__ float smem[];

    const int tid = threadIdx.x;
    const int wo  = tid & 3;          // 0..3  w octet (8 outputs each)
    const int hh  = (tid >> 2) & 7;   // 0..7  h within tile
    const int di  = tid >> 5;         // 0..8  h-shift index

    const int w0 = blockIdx.x * WB;
    const int h0 = blockIdx.y * HB;
    const int b  = blockIdx.z;

    const float* f1b = f1 + (size_t)b * CC_ * HH * WW;
    const float* f2b = f2 + (size_t)b * CC_ * HH * WW;

    const uint32_t smem_u32 = (uint32_t)__cvta_generic_to_shared(smem);

    // ---------- affine cp.async role assignment (per-thread constants) ----------
    // threads [0,160): one f2 granule (r, cg) walked over c = 0..15
    // threads [160,224): one f1 granule (h, cg) walked over c = 0..15
    // chunk positions swizzled: pos = cg ^ (row & 1)  (conflict-free windows)
    uint32_t g_src = 0, s_dst = 0;
    bool g_ok = false;
    const bool is_f2 = (tid < 160);
    const bool is_f1 = (tid >= 160) && (tid < 224);
    if (is_f2) {
        int r  = tid / 10;
        int cg = tid - r * 10;
        int gh = h0 + r - 4;
        int gw = w0 + cg * 4 - 4;
        g_ok  = (gh >= 0) && (gh < HH) && (gw >= 0) && (gw + 4 <= WW);
        g_src = g_ok ? (uint32_t)(gh * WW + gw) : 0u;
        s_dst = (uint32_t)((F1_ELEMS + r * F2P + ((cg ^ (r & 1)) << 2)) * 4);
    } else if (is_f1) {
        int u  = tid - 160;
        int h  = u >> 3;
        int cg = u & 7;
        g_ok  = true;
        g_src = (uint32_t)((h0 + h) * WW + w0 + cg * 4);
        s_dst = (uint32_t)((h * F1P + ((cg ^ (h & 1)) << 2)) * 4);
    }

    auto issue = [&](int ck, int buf) {
        const uint32_t stb = smem_u32 + buf * STAGE_BYTES;
        if (is_f2) {
            const float* src = f2b + (size_t)ck * CHUNK_ELEMS + g_src;
            uint32_t dst = stb + s_dst;
            #pragma unroll
            for (int c = 0; c < CCH; c++) {
                cp16(dst, src, g_ok);
                src += HH * WW;
                dst += F2_SLICE * 4;
            }
        } else if (is_f1) {
            const float* src = f1b + (size_t)ck * CHUNK_ELEMS + g_src;
            uint32_t dst = stb + s_dst;
            #pragma unroll
            for (int c = 0; c < CCH; c++) {
                cp16(dst, src, true);
                src += HH * WW;
                dst += F1_SLICE * 4;
            }
        }
        asm volatile("cp.async.commit_group;" ::: "memory");
    };

    // ------------- accumulators: 9 dj x 4 packed w-pairs (8 outputs) -------------
    u64 acc[SS][4];
    #pragma unroll
    for (int j = 0; j < SS; j++) {
        acc[j][0] = 0ULL; acc[j][1] = 0ULL; acc[j][2] = 0ULL; acc[j][3] = 0ULL;
    }

    // ---------- compute-side smem read offsets (swizzled chunk positions) ----------
    const int r2 = hh + di;                        // f2 row index
    const int rp = r2 & 1;
    const int hp = hh & 1;
    int f1o0 = hh * F1P + (((2 * wo + 0) ^ hp) << 2);
    int f1o1 = hh * F1P + (((2 * wo + 1) ^ hp) << 2);
    int f2o0 = F1_ELEMS + r2 * F2P + (((2 * wo + 0) ^ rp) << 2);
    int f2o1 = F1_ELEMS + r2 * F2P + (((2 * wo + 1) ^ rp) << 2);
    int f2o2 = F1_ELEMS + r2 * F2P + (((2 * wo + 2) ^ rp) << 2);
    int f2o3 = F1_ELEMS + r2 * F2P + (((2 * wo + 3) ^ rp) << 2);

    issue(0, 0);

    for (int ck = 0; ck < NCH; ck++) {
        if (ck + 1 < NCH) {
            issue(ck + 1, (ck + 1) & 1);
            asm volatile("cp.async.wait_group 1;" ::: "memory");
        } else {
            asm volatile("cp.async.wait_group 0;" ::: "memory");
        }
        __syncthreads();

        const float* st = smem + (ck & 1) * STAGE;

        #pragma unroll
        for (int c = 0; c < CCH; c++) {
            const float* s1 = st + c * F1_SLICE;
            const float* s2 = st + c * F2_SLICE;

            // ---- each 16B chunk loaded exactly ONCE (6 LDS.128 / c) ----
            float4 a0 = *reinterpret_cast<const float4*>(s1 + f1o0);
            float4 a1 = *reinterpret_cast<const float4*>(s1 + f1o1);
            float4 v0 = *reinterpret_cast<const float4*>(s2 + f2o0);
            float4 v1 = *reinterpret_cast<const float4*>(s2 + f2o1);
            float4 v2 = *reinterpret_cast<const float4*>(s2 + f2o2);
            float4 v3 = *reinterpret_cast<const float4*>(s2 + f2o3);

            // f1: 4 even-aligned pairs (register-coalescible packs)
            u64 pa0 = pack2(a0.x, a0.y);
            u64 pa1 = pack2(a0.z, a0.w);
            u64 pa2 = pack2(a1.x, a1.y);
            u64 pa3 = pack2(a1.z, a1.w);

            // f2: sliding-window pairs 0..14 built from registers
            u64 pv[15];
            pv[0]  = pack2(v0.x, v0.y);
            pv[1]  = pack2(v0.y, v0.z);
            pv[2]  = pack2(v0.z, v0.w);
            pv[3]  = pack2(v0.w, v1.x);
            pv[4]  = pack2(v1.x, v1.y);
            pv[5]  = pack2(v1.y, v1.z);
            pv[6]  = pack2(v1.z, v1.w);
            pv[7]  = pack2(v1.w, v2.x);
            pv[8]  = pack2(v2.x, v2.y);
            pv[9]  = pack2(v2.y, v2.z);
            pv[10] = pack2(v2.z, v2.w);
            pv[11] = pack2(v2.w, v3.x);
            pv[12] = pack2(v3.x, v3.y);
            pv[13] = pack2(v3.y, v3.z);
            pv[14] = pack2(v3.z, v3.w);

            #pragma unroll
            for (int dj = 0; dj < SS; dj++) {
                fma2(acc[dj][0], pa0, pv[dj]);       // outputs w+0,1
                fma2(acc[dj][1], pa1, pv[dj + 2]);   // outputs w+2,3
                fma2(acc[dj][2], pa2, pv[dj + 4]);   // outputs w+4,5
                fma2(acc[dj][3], pa3, pv[dj + 6]);   // outputs w+6,7
            }
        }
        __syncthreads();
    }

    // ------------------------- epilogue: scale + store -------------------------
    const float scale = 1.0f / (float)CC_;
    #pragma unroll
    for (int dj = 0; dj < SS; dj++) {
        int s = di * SS + dj;
        float x0, x1, x2, x3, x4, x5, x6, x7;
        unpack2(acc[dj][0], x0, x1);
        unpack2(acc[dj][1], x2, x3);
        unpack2(acc[dj][2], x4, x5);
        unpack2(acc[dj][3], x6, x7);
        float* dst = out + (((size_t)b * (SS * SS) + s) * HH + (h0 + hh)) * WW
                   + w0 + wo * 8;
        float4 o0, o1;
        o0.x = x0 * scale; o0.y = x1 * scale; o0.z = x2 * scale; o0.w = x3 * scale;
        o1.x = x4 * scale; o1.y = x5 * scale; o1.z = x6 * scale; o1.w = x7 * scale;
        *reinterpret_cast<float4*>(dst)     = o0;
        *reinterpret_cast<float4*>(dst + 4) = o1;
    }
}

extern "C" void kernel_launch(void* const* d_in, const int* in_sizes, int n_in,
                              void* d_out, int out_size) {
    const float* f1 = (const float*)d_in[0];
    const float* f2 = (const float*)d_in[1];
    float* out = (float*)d_out;

    cudaFuncSetAttribute(CostVolume_56745107914783_kernel,
                         cudaFuncAttributeMaxDynamicSharedMemorySize, SMEM_BYTES);

    dim3 grid(WW / WB, HH / HB, BB);   // 8 x 16 x 8 = 1024 CTAs
    CostVolume_56745107914783_kernel<<<grid, NT, SMEM_BYTES>>>(f1, f2, out);
}

// round 16
// speedup vs baseline: 1.0410x; 1.0065x over previous
#include <cuda_runtime.h>
#include <cstdint>

// CostVolume: B=8, C=128, H=128, W=256, d=4 -> out (8, 81, 128, 256) fp32
#define BB   8
#define CC_  128
#define HH   128
#define WW   256
#define SS   9

#define HB   8                 // h rows per CTA tile
#define WB   32                // w cols per CTA tile
#define CCH  16                // channel chunk
#define NCH  (CC_ / CCH)       // 8 chunks
#define F2R  16                // HB + 8 halo rows
#define F2P  40                // f2 row pitch (floats): 10 chunks of 16B
#define F1P  32                // f1 row pitch: 8 chunks
#define NT   288               // 9 di * 8 hh * 4 wo

#define F1_SLICE (HB * F1P)                 // 256 floats per channel
#define F1_ELEMS (CCH * F1_SLICE)           // 4096
#define F2_SLICE (F2R * F2P)                // 640 floats per channel
#define F2_ELEMS (CCH * F2_SLICE)           // 10240
#define STAGE       (F1_ELEMS + F2_ELEMS)   // 14336 floats
#define STAGE_BYTES (STAGE * 4)             // 57344 B
#define SMEM_BYTES  (2 * STAGE_BYTES)       // 114688 B -> 2 CTAs/SM (224KB)

#define CHUNK_ELEMS (CCH * HH * WW)         // 524288 per c-chunk

using u64 = unsigned long long;

__device__ __forceinline__ u64 pack2(float lo, float hi) {
    u64 r;
    asm("mov.b64 %0, {%1, %2};" : "=l"(r) : "f"(lo), "f"(hi));
    return r;
}
__device__ __forceinline__ void unpack2(u64 v, float& lo, float& hi) {
    asm("mov.b64 {%0, %1}, %2;" : "=f"(lo), "=f"(hi) : "l"(v));
}
__device__ __forceinline__ void fma2(u64& acc, u64 a, u64 b) {
    asm("fma.rn.f32x2 %0, %1, %2, %0;" : "+l"(acc) : "l"(a), "l"(b));
}
__device__ __forceinline__ void cp16(uint32_t dst, const void* src, bool ok) {
    int sz = ok ? 16 : 0;
    asm volatile("cp.async.cg.shared.global [%0], [%1], 16, %2;\n"
                 :: "r"(dst), "l"(src), "r"(sz) : "memory");
}

__global__ __launch_bounds__(NT, 2)
void CostVolume_56745107914783_kernel(const float* __restrict__ f1,
                                      const float* __restrict__ f2,
                                      float* __restrict__ out)
{
    extern __shared__ float smem[];

    const int tid = threadIdx.x;
    const int wo  = tid & 3;          // 0..3  w octet (8 outputs each)
    const int hh  = (tid >> 2) & 7;   // 0..7  h within tile
    const int di  = tid >> 5;         // 0..8  h-shift index

    const int w0 = blockIdx.x * WB;
    const int h0 = blockIdx.y * HB;
    const int b  = blockIdx.z;

    const float* f1b = f1 + (size_t)b * CC_ * HH * WW;
    const float* f2b = f2 + (size_t)b * CC_ * HH * WW;

    const uint32_t smem_u32 = (uint32_t)__cvta_generic_to_shared(smem);

    // ---------- affine cp.async role assignment (per-thread constants) ----------
    // threads [0,160): one f2 granule (r, cg) walked over c = 0..15
    // threads [160,224): one f1 granule (h, cg) walked over c = 0..15
    // chunk positions swizzled: pos = cg ^ (row & 1)  (conflict-free windows)
    uint32_t g_src = 0, s_dst = 0;
    bool g_ok = false;
    const bool is_f2 = (tid < 160);
    const bool is_f1 = (tid >= 160) && (tid < 224);
    if (is_f2) {
        int r  = tid / 10;
        int cg = tid - r * 10;
        int gh = h0 + r - 4;
        int gw = w0 + cg * 4 - 4;
        g_ok  = (gh >= 0) && (gh < HH) && (gw >= 0) && (gw + 4 <= WW);
        g_src = g_ok ? (uint32_t)(gh * WW + gw) : 0u;
        s_dst = (uint32_t)((F1_ELEMS + r * F2P + ((cg ^ (r & 1)) << 2)) * 4);
    } else if (is_f1) {
        int u  = tid - 160;
        int h  = u >> 3;
        int cg = u & 7;
        g_ok  = true;
        g_src = (uint32_t)((h0 + h) * WW + w0 + cg * 4);
        s_dst = (uint32_t)((h * F1P + ((cg ^ (h & 1)) << 2)) * 4);
    }

    auto issue = [&](int ck, int buf) {
        const uint32_t stb = smem_u32 + buf * STAGE_BYTES;
        if (is_f2) {
            const float* src = f2b + (size_t)ck * CHUNK_ELEMS + g_src;
            uint32_t dst = stb + s_dst;
            #pragma unroll
            for (int c = 0; c < CCH; c++) {
                cp16(dst, src, g_ok);
                src += HH * WW;
                dst += F2_SLICE * 4;
            }
        } else if (is_f1) {
            const float* src = f1b + (size_t)ck * CHUNK_ELEMS + g_src;
            uint32_t dst = stb + s_dst;
            #pragma unroll
            for (int c = 0; c < CCH; c++) {
                cp16(dst, src, true);
                src += HH * WW;
                dst += F1_SLICE * 4;
            }
        }
        asm volatile("cp.async.commit_group;" ::: "memory");
    };

    // ------------- accumulators: 9 dj x 4 packed w-pairs (8 outputs) -------------
    u64 acc[SS][4];
    #pragma unroll
    for (int j = 0; j < SS; j++) {
        acc[j][0] = 0ULL; acc[j][1] = 0ULL; acc[j][2] = 0ULL; acc[j][3] = 0ULL;
    }

    // ---------- compute-side smem read offsets (swizzled chunk positions) ----------
    const int r2 = hh + di;                        // f2 row index
    const int rp = r2 & 1;
    const int hp = hh & 1;
    int f1o0 = hh * F1P + (((2 * wo + 0) ^ hp) << 2);
    int f1o1 = hh * F1P + (((2 * wo + 1) ^ hp) << 2);
    int f2o0 = F1_ELEMS + r2 * F2P + (((2 * wo + 0) ^ rp) << 2);
    int f2o1 = F1_ELEMS + r2 * F2P + (((2 * wo + 1) ^ rp) << 2);
    int f2o2 = F1_ELEMS + r2 * F2P + (((2 * wo + 2) ^ rp) << 2);
    int f2o3 = F1_ELEMS + r2 * F2P + (((2 * wo + 3) ^ rp) << 2);

    issue(0, 0);

    for (int ck = 0; ck < NCH; ck++) {
        if (ck + 1 < NCH) {
            issue(ck + 1, (ck + 1) & 1);
            asm volatile("cp.async.wait_group 1;" ::: "memory");
        } else {
            asm volatile("cp.async.wait_group 0;" ::: "memory");
        }
        __syncthreads();

        const float* st = smem + (ck & 1) * STAGE;

        #pragma unroll
        for (int c = 0; c < CCH; c++) {
            const float* s1 = st + c * F1_SLICE;
            const float* s2 = st + c * F2_SLICE;

            // ---- each 16B chunk loaded exactly ONCE (6 LDS.128 / c) ----
            float4 a0 = *reinterpret_cast<const float4*>(s1 + f1o0);
            float4 a1 = *reinterpret_cast<const float4*>(s1 + f1o1);
            float4 v0 = *reinterpret_cast<const float4*>(s2 + f2o0);
            float4 v1 = *reinterpret_cast<const float4*>(s2 + f2o1);
            float4 v2 = *reinterpret_cast<const float4*>(s2 + f2o2);
            float4 v3 = *reinterpret_cast<const float4*>(s2 + f2o3);

            // f1: 4 even-aligned pairs (register-coalescible packs)
            u64 pa0 = pack2(a0.x, a0.y);
            u64 pa1 = pack2(a0.z, a0.w);
            u64 pa2 = pack2(a1.x, a1.y);
            u64 pa3 = pack2(a1.z, a1.w);

            // f2: sliding-window pairs 0..14 built from registers
            u64 pv[15];
            pv[0]  = pack2(v0.x, v0.y);
            pv[1]  = pack2(v0.y, v0.z);
            pv[2]  = pack2(v0.z, v0.w);
            pv[3]  = pack2(v0.w, v1.x);
            pv[4]  = pack2(v1.x, v1.y);
            pv[5]  = pack2(v1.y, v1.z);
            pv[6]  = pack2(v1.z, v1.w);
            pv[7]  = pack2(v1.w, v2.x);
            pv[8]  = pack2(v2.x, v2.y);
            pv[9]  = pack2(v2.y, v2.z);
            pv[10] = pack2(v2.z, v2.w);
            pv[11] = pack2(v2.w, v3.x);
            pv[12] = pack2(v3.x, v3.y);
            pv[13] = pack2(v3.y, v3.z);
            pv[14] = pack2(v3.z, v3.w);

            #pragma unroll
            for (int dj = 0; dj < SS; dj++) {
                fma2(acc[dj][0], pa0, pv[dj]);       // outputs w+0,1
                fma2(acc[dj][1], pa1, pv[dj + 2]);   // outputs w+2,3
                fma2(acc[dj][2], pa2, pv[dj + 4]);   // outputs w+4,5
                fma2(acc[dj][3], pa3, pv[dj + 6]);   // outputs w+6,7
            }
        }
        __syncthreads();
    }

    // ------------------------- epilogue: scale + store -------------------------
    const float scale = 1.0f / (float)CC_;
    #pragma unroll
    for (int dj = 0; dj < SS; dj++) {
        int s = di * SS + dj;
        float x0, x1, x2, x3, x4, x5, x6, x7;
        unpack2(acc[dj][0], x0, x1);
        unpack2(acc[dj][1], x2, x3);
        unpack2(acc[dj][2], x4, x5);
        unpack2(acc[dj][3], x6, x7);
        float* dst = out + (((size_t)b * (SS * SS) + s) * HH + (h0 + hh)) * WW
                   + w0 + wo * 8;
        float4 o0, o1;
        o0.x = x0 * scale; o0.y = x1 * scale; o0.z = x2 * scale; o0.w = x3 * scale;
        o1.x = x4 * scale; o1.y = x5 * scale; o1.z = x6 * scale; o1.w = x7 * scale;
        *reinterpret_cast<float4*>(dst)     = o0;
        *reinterpret_cast<float4*>(dst + 4) = o1;
    }
}

extern "C" void kernel_launch(void* const* d_in, const int* in_sizes, int n_in,
                              void* d_out, int out_size) {
    const float* f1 = (const float*)d_in[0];
    const float* f2 = (const float*)d_in[1];
    float* out = (float*)d_out;

    cudaFuncSetAttribute(CostVolume_56745107914783_kernel,
                         cudaFuncAttributeMaxDynamicSharedMemorySize, SMEM_BYTES);

    dim3 grid(WW / WB, HH / HB, BB);   // 8 x 16 x 8 = 1024 CTAs
    CostVolume_56745107914783_kernel<<<grid, NT, SMEM_BYTES>>>(f1, f2, out);
}

// round 17
// speedup vs baseline: 1.4649x; 1.4072x over previous
#include <cuda_runtime.h>
#include <cuda.h>
#include <cstdint>

// CostVolume: B=8, C=128, H=128, W=256, d=4 -> out (8, 81, 128, 256) fp32
#define BB   8
#define CC_  128
#define HH   128
#define WW   256
#define SS   9

#define HB   8                  // h rows per CTA tile
#define WB   32                 // w cols per CTA tile
#define CCH  8                  // channels per chunk
#define NCK  16                 // chunks
#define F2ROWS 16               // HB + 8 halo rows
#define F2P  44                 // f2 TMA box width (40 used + 4 pad; bank-balanced)
#define F1P  36                 // f1 TMA box width (32 used + 4 pad; bank-balanced)
#define NT   288                // 9 di * 8 hh * 4 wo

#define F2_SLICE (F2ROWS * F2P)          // 704 floats per channel
#define F1_SLICE (HB * F1P)              // 288 floats per channel
#define F2_CH (CCH * F2_SLICE)           // 5632
#define F1_CH (CCH * F1_SLICE)           // 2304
#define STAGE (F2_CH + F1_CH)            // 7936 floats
#define STAGE_BYTES (STAGE * 4)          // 31744 B
#define NSTAGE 3
#define SMEM_BYTES (NSTAGE * STAGE_BYTES + 64)   // 95296 B -> 2 CTAs/SM

using u64 = unsigned long long;

__device__ __forceinline__ u64 pack2(float lo, float hi) {
    u64 r;
    asm("mov.b64 %0, {%1, %2};" : "=l"(r) : "f"(lo), "f"(hi));
    return r;
}
__device__ __forceinline__ void unpack2(u64 v, float& lo, float& hi) {
    asm("mov.b64 {%0, %1}, %2;" : "=f"(lo), "=f"(hi) : "l"(v));
}
__device__ __forceinline__ void fma2(u64& acc, u64 a, u64 b) {
    asm("fma.rn.f32x2 %0, %1, %2, %0;" : "+l"(acc) : "l"(a), "l"(b));
}

__device__ __forceinline__ void mbar_init(uint32_t mbar, uint32_t count) {
    asm volatile("mbarrier.init.shared.b64 [%0], %1;" :: "r"(mbar), "r"(count) : "memory");
}
__device__ __forceinline__ void mbar_expect_tx(uint32_t mbar, uint32_t bytes) {
    asm volatile("mbarrier.arrive.expect_tx.shared.b64 _, [%0], %1;"
                 :: "r"(mbar), "r"(bytes) : "memory");
}
__device__ __forceinline__ void mbar_wait(uint32_t mbar, int parity) {
    asm volatile(
        "{\n\t"
        ".reg .pred P;\n"
        "W%=:\n\t"
        "mbarrier.try_wait.parity.shared.b64 P, [%0], %1, 0x989680;\n\t"
        "@!P bra W%=;\n\t"
        "}"
        :: "r"(mbar), "r"(parity) : "memory");
}
__device__ __forceinline__ void tma3d(uint32_t dst, const CUtensorMap* tmap,
                                      int x, int y, int z, uint32_t mbar) {
    asm volatile(
        "cp.async.bulk.tensor.3d.shared::cta.global.tile.mbarrier::complete_tx::bytes "
        "[%0], [%1, {%2, %3, %4}], [%5];"
        :: "r"(dst), "l"(tmap), "r"(x), "r"(y), "r"(z), "r"(mbar) : "memory");
}
__device__ __forceinline__ void fence_async() {
    asm volatile("fence.proxy.async.shared::cta;" ::: "memory");
}

__global__ __launch_bounds__(NT, 2)
void CostVolume_56745107914783_kernel(const __grid_constant__ CUtensorMap tm2,
                                      const __grid_constant__ CUtensorMap tm1,
                                      float* __restrict__ out)
{
    extern __shared__ float smem[];
    const uint32_t smem_u32 = (uint32_t)__cvta_generic_to_shared(smem);
    const uint32_t mbar_base = smem_u32 + NSTAGE * STAGE_BYTES;

    const int tid = threadIdx.x;
    const int wo  = tid & 3;          // 0..3  w octet (8 outputs each)
    const int hh  = (tid >> 2) & 7;   // 0..7  h within tile
    const int di  = tid >> 5;         // 0..8  h-shift index

    const int w0 = blockIdx.x * WB;
    const int h0 = blockIdx.y * HB;
    const int b  = blockIdx.z;
    const int zb = b * CC_;           // z-coordinate base (b*128 + c)

    // ---- init pipeline barriers ----
    if (tid == 0) {
        mbar_init(mbar_base + 0, 1);
        mbar_init(mbar_base + 8, 1);
        mbar_init(mbar_base + 16, 1);
    }
    __syncthreads();

    // ---- prologue: prefetch chunks 0 and 1 ----
    if (tid == 0) {
        #pragma unroll
        for (int k = 0; k < 2; k++) {
            uint32_t stb = smem_u32 + k * STAGE_BYTES;
            mbar_expect_tx(mbar_base + k * 8, STAGE_BYTES);
            tma3d(stb,              &tm2, w0 - 4, h0 - 4, zb + k * CCH, mbar_base + k * 8);
            tma3d(stb + F2_CH * 4,  &tm1, w0,     h0,     zb + k * CCH, mbar_base + k * 8);
        }
    }

    // ---- accumulators: 9 dj x 4 packed w-pairs (8 outputs/thread) ----
    u64 acc[SS][4];
    #pragma unroll
    for (int j = 0; j < SS; j++) {
        acc[j][0] = 0ULL; acc[j][1] = 0ULL; acc[j][2] = 0ULL; acc[j][3] = 0ULL;
    }

    // smem read word-offsets (bank-balanced by pitch choice, no swizzle)
    const int r2  = hh + di;                       // f2 row 0..15
    const int f2o = r2 * F2P + wo * 8;             // window chunk 0 of 4
    const int f1o = hh * F1P + wo * 8;             // f1 chunk 0 of 2

    int s_use = 0, p_use = 0;   // consume stage/parity
    int s_iss = 2;              // stage receiving chunk ck+2

    for (int ck = 0; ck < NCK; ck++) {
        if (tid == 0 && ck + 2 < NCK) {
            fence_async();
            uint32_t stb = smem_u32 + s_iss * STAGE_BYTES;
            uint32_t mb  = mbar_base + s_iss * 8;
            mbar_expect_tx(mb, STAGE_BYTES);
            tma3d(stb,             &tm2, w0 - 4, h0 - 4, zb + (ck + 2) * CCH, mb);
            tma3d(stb + F2_CH * 4, &tm1, w0,     h0,     zb + (ck + 2) * CCH, mb);
        }

        mbar_wait(mbar_base + s_use * 8, p_use);

        const float* st = smem + s_use * STAGE;

        #pragma unroll
        for (int c = 0; c < CCH; c++) {
            const float* s2 = st + c * F2_SLICE + f2o;
            const float* s1 = st + F2_CH + c * F1_SLICE + f1o;

            // each 16B chunk loaded exactly once: 6 LDS.128 per c
            float4 a0 = *reinterpret_cast<const float4*>(s1);
            float4 a1 = *reinterpret_cast<const float4*>(s1 + 4);
            float4 v0 = *reinterpret_cast<const float4*>(s2);
            float4 v1 = *reinterpret_cast<const float4*>(s2 + 4);
            float4 v2 = *reinterpret_cast<const float4*>(s2 + 8);
            float4 v3 = *reinterpret_cast<const float4*>(s2 + 12);

            u64 pa0 = pack2(a0.x, a0.y);
            u64 pa1 = pack2(a0.z, a0.w);
            u64 pa2 = pack2(a1.x, a1.y);
            u64 pa3 = pack2(a1.z, a1.w);

            u64 pv[15];
            pv[0]  = pack2(v0.x, v0.y);
            pv[1]  = pack2(v0.y, v0.z);
            pv[2]  = pack2(v0.z, v0.w);
            pv[3]  = pack2(v0.w, v1.x);
            pv[4]  = pack2(v1.x, v1.y);
            pv[5]  = pack2(v1.y, v1.z);
            pv[6]  = pack2(v1.z, v1.w);
            pv[7]  = pack2(v1.w, v2.x);
            pv[8]  = pack2(v2.x, v2.y);
            pv[9]  = pack2(v2.y, v2.z);
            pv[10] = pack2(v2.z, v2.w);
            pv[11] = pack2(v2.w, v3.x);
            pv[12] = pack2(v3.x, v3.y);
            pv[13] = pack2(v3.y, v3.z);
            pv[14] = pack2(v3.z, v3.w);

            #pragma unroll
            for (int dj = 0; dj < SS; dj++) {
                fma2(acc[dj][0], pa0, pv[dj]);       // outputs w+0,1
                fma2(acc[dj][1], pa1, pv[dj + 2]);   // outputs w+2,3
                fma2(acc[dj][2], pa2, pv[dj + 4]);   // outputs w+4,5
                fma2(acc[dj][3], pa3, pv[dj + 6]);   // outputs w+6,7
            }
        }
        __syncthreads();   // all reads of stage s_use done -> safe to re-fill

        if (++s_use == NSTAGE) { s_use = 0; p_use ^= 1; }
        if (++s_iss == NSTAGE) s_iss = 0;
    }

    // ---- epilogue: scale + store ----
    const float scale = 1.0f / (float)CC_;
    #pragma unroll
    for (int dj = 0; dj < SS; dj++) {
        int s = di * SS + dj;
        float x0, x1, x2, x3, x4, x5, x6, x7;
        unpack2(acc[dj][0], x0, x1);
        unpack2(acc[dj][1], x2, x3);
        unpack2(acc[dj][2], x4, x5);
        unpack2(acc[dj][3], x6, x7);
        float* dst = out + (((size_t)b * (SS * SS) + s) * HH + (h0 + hh)) * WW
                   + w0 + wo * 8;
        float4 o0, o1;
        o0.x = x0 * scale; o0.y = x1 * scale; o0.z = x2 * scale; o0.w = x3 * scale;
        o1.x = x4 * scale; o1.y = x5 * scale; o1.z = x6 * scale; o1.w = x7 * scale;
        *reinterpret_cast<float4*>(dst)     = o0;
        *reinterpret_cast<float4*>(dst + 4) = o1;
    }
}

// ----------------------------- host side -----------------------------
typedef CUresult (*PFN_encode)(CUtensorMap*, CUtensorMapDataType, cuuint32_t, void*,
                               const cuuint64_t*, const cuuint64_t*, const cuuint32_t*,
                               const cuuint32_t*, CUtensorMapInterleave, CUtensorMapSwizzle,
                               CUtensorMapL2promotion, CUtensorMapFloatOOBfill);

static void encode_map(PFN_encode enc, CUtensorMap* tm, void* base,
                       uint32_t bx, uint32_t by, uint32_t bz) {
    cuuint64_t dims[3]    = { (cuuint64_t)WW, (cuuint64_t)HH, (cuuint64_t)(BB * CC_) };
    cuuint64_t strides[2] = { (cuuint64_t)WW * 4, (cuuint64_t)HH * WW * 4 };
    cuuint32_t box[3]     = { bx, by, bz };
    cuuint32_t estr[3]    = { 1, 1, 1 };
    enc(tm, CU_TENSOR_MAP_DATA_TYPE_FLOAT32, 3, base, dims, strides, box, estr,
        CU_TENSOR_MAP_INTERLEAVE_NONE, CU_TENSOR_MAP_SWIZZLE_NONE,
        CU_TENSOR_MAP_L2_PROMOTION_L2_128B, CU_TENSOR_MAP_FLOAT_OOB_FILL_NONE);
}

extern "C" void kernel_launch(void* const* d_in, const int* in_sizes, int n_in,
                              void* d_out, int out_size) {
    void* f1 = d_in[0];
    void* f2 = d_in[1];
    float* out = (float*)d_out;

    // driver entry point via cudart (no -lcuda link dependency)
    void* fn = nullptr;
    cudaDriverEntryPointQueryResult qr;
    cudaGetDriverEntryPointByVersion("cuTensorMapEncodeTiled", &fn, 12000,
                                     cudaEnableDefault, &qr);
    PFN_encode enc = (PFN_encode)fn;

    CUtensorMap tm2, tm1;
    encode_map(enc, &tm2, f2, F2P, F2ROWS, CCH);   // f2: 44 x 16 x 8 box
    encode_map(enc, &tm1, f1, F1P, HB,    CCH);    // f1: 36 x  8 x 8 box

    cudaFuncSetAttribute(CostVolume_56745107914783_kernel,
                         cudaFuncAttributeMaxDynamicSharedMemorySize, SMEM_BYTES);

    dim3 grid(WW / WB, HH / HB, BB);   // 8 x 16 x 8 = 1024 CTAs
    CostVolume_56745107914783_kernel<<<grid, NT, SMEM_BYTES>>>(tm2, tm1, out);
}